// round 5
// baseline (speedup 1.0000x reference)
#include <cuda_runtime.h>
#include <cuda_bf16.h>
#include <math.h>
#include <stdint.h>

// Problem constants
#define DIMM   768
#define NHEAD  12
#define HDIM   64
#define BATCH  2
#define GRID_H 48
#define NSEQ   2304          // 48*48
#define BHN    24            // BATCH*NHEAD
#define MROWS  4608          // BATCH*NSEQ
#define SCALE  0.125f        // 64^-0.5

// ---------------- device scratch (static: no cudaMalloc allowed) ----------------
__device__ float g_q[BHN * NSEQ * HDIM];       // [bh][n][c], unscaled
__device__ float g_k[BHN * NSEQ * HDIM];
__device__ float g_v[BHN * NSEQ * HDIM];
__device__ float g_relh[BHN * NSEQ * GRID_H];  // [bh][q][kh]
__device__ float g_relw[BHN * NSEQ * GRID_H];  // [bh][q][kw]
__device__ float g_ao[MROWS * DIMM];           // attention output (b,n,dim)

// ---------------- tf32 helpers ----------------
__device__ __forceinline__ uint32_t f2tf32(float f) {
    uint32_t r;
    asm("cvt.rna.tf32.f32 %0, %1;" : "=r"(r) : "f"(f));
    return r;
}
__device__ __forceinline__ float tf32f(float f) { return __uint_as_float(f2tf32(f)); }

// D(16x8,f32) += A(16x8,tf32,row) * B(8x8,tf32,col)
__device__ __forceinline__ void mma_tf32(float* d, const uint32_t* a,
                                         uint32_t b0, uint32_t b1) {
    asm volatile(
        "mma.sync.aligned.m16n8k8.row.col.f32.tf32.tf32.f32 "
        "{%0,%1,%2,%3}, {%4,%5,%6,%7}, {%8,%9}, {%0,%1,%2,%3};"
        : "+f"(d[0]), "+f"(d[1]), "+f"(d[2]), "+f"(d[3])
        : "r"(a[0]), "r"(a[1]), "r"(a[2]), "r"(a[3]), "r"(b0), "r"(b1));
}

// =================================================================
// tf32 tensor-core GEMM NT, double-buffered (1 sync / k-step).
// C[M,N] = A[M,K] * B[N,K]^T (+bias). 128x128x16 tiles, 8 warps.
// MODE 0: QKV epilogue scattering to g_q/g_k/g_v. MODE 1: A=g_ao.
// =================================================================
#define GPAD 20

template<int MODE>
__global__ __launch_bounds__(256, 2) void gemm_tc(const float* __restrict__ Aext,
                                                  const float* __restrict__ B,
                                                  const float* __restrict__ bias,
                                                  float* __restrict__ Cout,
                                                  int Ncol, int K)
{
    __shared__ float As[2][128][GPAD];
    __shared__ float Bs[2][128][GPAD];
    const float* A = (MODE == 0) ? Aext : (const float*)g_ao;

    const int m0 = blockIdx.y * 128;
    const int n0 = blockIdx.x * 128;
    const int tid = threadIdx.x;
    const int lane = tid & 31;
    const int wid = tid >> 5;
    const int wm = (wid & 1) * 64;   // warp m-offset
    const int wn = (wid >> 1) * 32;  // warp n-offset
    const int gr = lane >> 2;        // 0..7
    const int gc = lane & 3;         // 0..3
    const int sr = tid >> 2;         // staging row 0..63
    const int sc = (tid & 3) << 2;   // staging col 0,4,8,12

    float acc[4][4][4];
#pragma unroll
    for (int mi = 0; mi < 4; mi++)
#pragma unroll
        for (int ni = 0; ni < 4; ni++)
#pragma unroll
            for (int j = 0; j < 4; j++) acc[mi][ni][j] = 0.f;

    // stage helper (LDG -> tf32 -> STS), transient registers
    auto stage = [&](int k0, int pb) {
        float4 av0 = *(const float4*)(A + (size_t)(m0 + sr) * K + k0 + sc);
        float4 av1 = *(const float4*)(A + (size_t)(m0 + sr + 64) * K + k0 + sc);
        float4 bv0 = *(const float4*)(B + (size_t)(n0 + sr) * K + k0 + sc);
        float4 bv1 = *(const float4*)(B + (size_t)(n0 + sr + 64) * K + k0 + sc);
        As[pb][sr][sc + 0] = tf32f(av0.x); As[pb][sr][sc + 1] = tf32f(av0.y);
        As[pb][sr][sc + 2] = tf32f(av0.z); As[pb][sr][sc + 3] = tf32f(av0.w);
        As[pb][sr + 64][sc + 0] = tf32f(av1.x); As[pb][sr + 64][sc + 1] = tf32f(av1.y);
        As[pb][sr + 64][sc + 2] = tf32f(av1.z); As[pb][sr + 64][sc + 3] = tf32f(av1.w);
        Bs[pb][sr][sc + 0] = tf32f(bv0.x); Bs[pb][sr][sc + 1] = tf32f(bv0.y);
        Bs[pb][sr][sc + 2] = tf32f(bv0.z); Bs[pb][sr][sc + 3] = tf32f(bv0.w);
        Bs[pb][sr + 64][sc + 0] = tf32f(bv1.x); Bs[pb][sr + 64][sc + 1] = tf32f(bv1.y);
        Bs[pb][sr + 64][sc + 2] = tf32f(bv1.z); Bs[pb][sr + 64][sc + 3] = tf32f(bv1.w);
    };

    stage(0, 0);
    __syncthreads();

    const int nk = K / 16;
    for (int kt = 0; kt < nk; kt++) {
        const int p = kt & 1;
        if (kt + 1 < nk) stage((kt + 1) * 16, p ^ 1);

#pragma unroll
        for (int kk = 0; kk < 16; kk += 8) {
            uint32_t af[4][4], bf[4][2];
#pragma unroll
            for (int mi = 0; mi < 4; mi++) {
                const float* ap = &As[p][wm + mi * 16 + gr][kk + gc];
                af[mi][0] = __float_as_uint(ap[0]);
                af[mi][1] = __float_as_uint(ap[8 * GPAD]);
                af[mi][2] = __float_as_uint(ap[4]);
                af[mi][3] = __float_as_uint(ap[8 * GPAD + 4]);
            }
#pragma unroll
            for (int ni = 0; ni < 4; ni++) {
                const float* bp = &Bs[p][wn + ni * 8 + gr][kk + gc];
                bf[ni][0] = __float_as_uint(bp[0]);
                bf[ni][1] = __float_as_uint(bp[4]);
            }
#pragma unroll
            for (int mi = 0; mi < 4; mi++)
#pragma unroll
                for (int ni = 0; ni < 4; ni++)
                    mma_tf32(acc[mi][ni], af[mi], bf[ni][0], bf[ni][1]);
        }
        __syncthreads();
    }

    // ---- epilogue
#pragma unroll
    for (int ni = 0; ni < 4; ni++) {
        const int nb = n0 + wn + ni * 8 + 2 * gc;
        const float bbx = bias[nb], bby = bias[nb + 1];
        if (MODE == 0) {
            const int p = nb / DIMM;
            const int hh = (nb % DIMM) / HDIM;
            const int cb = nb % HDIM;
            float* dst = (p == 0) ? g_q : ((p == 1) ? g_k : g_v);
#pragma unroll
            for (int mi = 0; mi < 4; mi++) {
                int m = m0 + wm + mi * 16 + gr;
                int b = m / NSEQ, nn = m % NSEQ;
                float* d0 = dst + (size_t)((b * NHEAD + hh) * NSEQ + nn) * HDIM + cb;
                *(float2*)d0 = make_float2(acc[mi][ni][0] + bbx, acc[mi][ni][1] + bby);
                int m2 = m + 8;
                int b2 = m2 / NSEQ, nn2 = m2 % NSEQ;
                float* d1 = dst + (size_t)((b2 * NHEAD + hh) * NSEQ + nn2) * HDIM + cb;
                *(float2*)d1 = make_float2(acc[mi][ni][2] + bbx, acc[mi][ni][3] + bby);
            }
        } else {
#pragma unroll
            for (int mi = 0; mi < 4; mi++) {
                int m = m0 + wm + mi * 16 + gr;
                *(float2*)(Cout + (size_t)m * Ncol + nb) =
                    make_float2(acc[mi][ni][0] + bbx, acc[mi][ni][1] + bby);
                *(float2*)(Cout + (size_t)(m + 8) * Ncol + nb) =
                    make_float2(acc[mi][ni][2] + bbx, acc[mi][ni][3] + bby);
            }
        }
    }
}

// =================================================================
// rel bias tables (unchanged)
// =================================================================
#define REL_SMEM ((3072 + 3072 + 6080) * 4)

__global__ __launch_bounds__(256) void rel_kernel(const float* __restrict__ rph,
                                                  const float* __restrict__ rpw)
{
    extern __shared__ float sm[];
    float* qs = sm;            // [48][64]
    float* rh = sm + 3072;     // [48][64]
    float* rw = sm + 6144;     // [95][64]

    const int qh = blockIdx.x;
    const int bh = blockIdx.y;
    const int tid = threadIdx.x;

    const float4* qsrc = (const float4*)(g_q + (size_t)(bh * NSEQ + qh * GRID_H) * HDIM);
#pragma unroll
    for (int i = 0; i < 3; i++) ((float4*)qs)[tid + i * 256] = qsrc[tid + i * 256];

    for (int i = tid; i < 768; i += 256) {
        int kh = i >> 4, cc = i & 15;
        ((float4*)rh)[i] = ((const float4*)(rph + (size_t)(qh - kh + 47) * HDIM))[cc];
    }
    for (int i = tid; i < 1520; i += 256) ((float4*)rw)[i] = ((const float4*)rpw)[i];
    __syncthreads();

    for (int idx = tid; idx < 2304; idx += 256) {
        int qw = idx / GRID_H;
        int kk = idx - qw * GRID_H;
        const float4* qp = (const float4*)(qs + qw * HDIM);
        const float4* hp = (const float4*)(rh + kk * HDIM);
        const float4* wp = (const float4*)(rw + (qw - kk + 47) * HDIM);
        float sh = 0.f, sw2 = 0.f;
#pragma unroll
        for (int c = 0; c < 16; c++) {
            float4 a = qp[c], hb = hp[c], wb = wp[c];
            sh  += a.x * hb.x + a.y * hb.y + a.z * hb.z + a.w * hb.w;
            sw2 += a.x * wb.x + a.y * wb.y + a.z * wb.z + a.w * wb.w;
        }
        size_t base = ((size_t)bh * NSEQ + (size_t)qh * GRID_H + qw) * GRID_H + kk;
        g_relh[base] = sh;
        g_relw[base] = sw2;
    }
}

// =================================================================
// Flash attention, tf32 mma, double-buffered K/V (1 sync/iter),
// P kept in registers via fragment shuffle, bf16 rel bias.
// 128-q tile, 8 warps, 96KB smem -> 2 CTAs/SM.
// =================================================================
#define KS 68   // ≡ 4 (mod 32)
#define VS 72   // ≡ 8 (mod 32)
#define RLS 52
#define FLASH_TC_SMEM (2*64*KS*4 + 2*64*VS*4 + 2*128*RLS*2)

__global__ __launch_bounds__(256, 2) void flash_tc()
{
    extern __shared__ char smraw[];
    float* Kb = (float*)smraw;                          // [2][64*KS]
    float* Vb = (float*)(smraw + 2 * 64 * KS * 4);      // [2][64*VS]
    __nv_bfloat16* RHb = (__nv_bfloat16*)(smraw + 2 * 64 * KS * 4 + 2 * 64 * VS * 4);
    __nv_bfloat16* RWb = RHb + 128 * RLS;

    const int bh = blockIdx.y;
    const int q0 = blockIdx.x * 128;
    const int tid = threadIdx.x;
    const int lane = tid & 31;
    const int wid = tid >> 5;
    const int wrow = wid * 16;          // warp's q-row stripe base (tile-local)
    const int gr = lane >> 2;           // 0..7
    const int gc = lane & 3;            // 0..3
    const int srcLo = 4 * gr + (gc >> 1);
    const int srcHi = srcLo + 2;
    const int sel = gc & 1;

    const float* qg = g_q + (size_t)bh * NSEQ * HDIM;
    const float* kg = g_k + (size_t)bh * NSEQ * HDIM;
    const float* vg = g_v + (size_t)bh * NSEQ * HDIM;

    const int ldrow = tid >> 2;          // 0..63 (K/V staging row)
    const int ldc0 = (tid & 3) * 16;     // 16-col slice

    // stage K/V tile -> buffer pb (tf32-rounded)
    auto stage = [&](int tile, int pb) {
        const float* krow = kg + ((size_t)(tile * 64 + ldrow)) * HDIM + ldc0;
        const float* vrow = vg + ((size_t)(tile * 64 + ldrow)) * HDIM + ldc0;
        float* kd = Kb + pb * 64 * KS + ldrow * KS + ldc0;
        float* vd = Vb + pb * 64 * VS + ldrow * VS + ldc0;
#pragma unroll
        for (int i = 0; i < 4; i++) {
            float4 kv = *(const float4*)(krow + i * 4);
            float4 vv = *(const float4*)(vrow + i * 4);
            *(float4*)(kd + i * 4) = make_float4(tf32f(kv.x), tf32f(kv.y), tf32f(kv.z), tf32f(kv.w));
            *(float4*)(vd + i * 4) = make_float4(tf32f(vv.x), tf32f(vv.y), tf32f(vv.z), tf32f(vv.w));
        }
    };

    // ---- Q fragments: scaled, tf32-rounded, registers for all iters
    uint32_t qa[8][4];
    {
        const float* qr0 = qg + (size_t)(q0 + wrow + gr) * HDIM;
        const float* qr1 = qr0 + 8 * HDIM;
#pragma unroll
        for (int ks = 0; ks < 8; ks++) {
            qa[ks][0] = f2tf32(qr0[ks * 8 + gc] * SCALE);
            qa[ks][1] = f2tf32(qr1[ks * 8 + gc] * SCALE);
            qa[ks][2] = f2tf32(qr0[ks * 8 + gc + 4] * SCALE);
            qa[ks][3] = f2tf32(qr1[ks * 8 + gc + 4] * SCALE);
        }
    }

    // ---- rel bias slices -> bf16 SMEM [128][48] (stride 52)
    {
        const float4* srcH = (const float4*)(g_relh + ((size_t)bh * NSEQ + q0) * GRID_H);
        const float4* srcW = (const float4*)(g_relw + ((size_t)bh * NSEQ + q0) * GRID_H);
        for (int i = tid; i < 1536; i += 256) {   // 128 rows * 12 float4/row
            int r = i / 12, c4 = i % 12;
            float4 vh = srcH[i], vw = srcW[i];
            __nv_bfloat162* dh = (__nv_bfloat162*)(RHb + r * RLS + c4 * 4);
            __nv_bfloat162* dw = (__nv_bfloat162*)(RWb + r * RLS + c4 * 4);
            dh[0] = __floats2bfloat162_rn(vh.x, vh.y);
            dh[1] = __floats2bfloat162_rn(vh.z, vh.w);
            dw[0] = __floats2bfloat162_rn(vw.x, vw.y);
            dw[1] = __floats2bfloat162_rn(vw.z, vw.w);
        }
    }

    stage(0, 0);
    __syncthreads();

    float o[8][4];
    float m0r = -1e30f, m1r = -1e30f, l0r = 0.f, l1r = 0.f;
#pragma unroll
    for (int nt = 0; nt < 8; nt++)
#pragma unroll
        for (int j = 0; j < 4; j++) o[nt][j] = 0.f;

    const int NIT = NSEQ / 64;   // 36
    for (int it = 0; it < NIT; it++) {
        const int p = it & 1;
        // stage next tile into the other buffer (overlaps with compute)
        if (it + 1 < NIT) stage(it + 1, p ^ 1);

        const float* Kp = Kb + p * 64 * KS;
        const float* Vp = Vb + p * 64 * VS;
        const int k0 = it * 64;

        // ---- S = Q @ K^T
        float s[8][4];
#pragma unroll
        for (int nt = 0; nt < 8; nt++) {
            s[nt][0] = s[nt][1] = s[nt][2] = s[nt][3] = 0.f;
            const uint32_t* kb = (const uint32_t*)(Kp + (nt * 8 + gr) * KS);
#pragma unroll
            for (int ks = 0; ks < 8; ks++)
                mma_tf32(s[nt], qa[ks], kb[ks * 8 + gc], kb[ks * 8 + gc + 4]);
        }

        // ---- add decomposed rel-pos bias (bf16)
        {
            const __nv_bfloat16* rh0 = RHb + (wrow + gr) * RLS;
            const __nv_bfloat16* rw0 = RWb + (wrow + gr) * RLS;
            const __nv_bfloat16* rh1 = rh0 + 8 * RLS;
            const __nv_bfloat16* rw1 = rw0 + 8 * RLS;
#pragma unroll
            for (int nt = 0; nt < 8; nt++) {
                int c0 = k0 + nt * 8 + 2 * gc;
                int kh0 = c0 / GRID_H, kw0 = c0 - kh0 * GRID_H;
                int c1 = c0 + 1;
                int kh1 = c1 / GRID_H, kw1 = c1 - kh1 * GRID_H;
                s[nt][0] += __bfloat162float(rh0[kh0]) + __bfloat162float(rw0[kw0]);
                s[nt][1] += __bfloat162float(rh0[kh1]) + __bfloat162float(rw0[kw1]);
                s[nt][2] += __bfloat162float(rh1[kh0]) + __bfloat162float(rw1[kw0]);
                s[nt][3] += __bfloat162float(rh1[kh1]) + __bfloat162float(rw1[kw1]);
            }
        }

        // ---- online softmax (rows wrow+gr, wrow+gr+8)
        float t0 = -1e30f, t1 = -1e30f;
#pragma unroll
        for (int nt = 0; nt < 8; nt++) {
            t0 = fmaxf(t0, fmaxf(s[nt][0], s[nt][1]));
            t1 = fmaxf(t1, fmaxf(s[nt][2], s[nt][3]));
        }
        t0 = fmaxf(t0, __shfl_xor_sync(0xffffffffu, t0, 1));
        t0 = fmaxf(t0, __shfl_xor_sync(0xffffffffu, t0, 2));
        t1 = fmaxf(t1, __shfl_xor_sync(0xffffffffu, t1, 1));
        t1 = fmaxf(t1, __shfl_xor_sync(0xffffffffu, t1, 2));

        float mn0 = fmaxf(m0r, t0), mn1 = fmaxf(m1r, t1);
        float c0f = __expf(m0r - mn0), c1f = __expf(m1r - mn1);
        m0r = mn0; m1r = mn1;

        // ---- exp, row-sum, and P -> A-fragment layout via shuffles
        uint32_t pf[8][4];
        float rs0 = 0.f, rs1 = 0.f;
#pragma unroll
        for (int nt = 0; nt < 8; nt++) {
            float p0 = __expf(s[nt][0] - mn0);
            float p1 = __expf(s[nt][1] - mn0);
            float p2 = __expf(s[nt][2] - mn1);
            float p3 = __expf(s[nt][3] - mn1);
            rs0 += p0 + p1;
            rs1 += p2 + p3;
            uint32_t u0 = f2tf32(p0), u1 = f2tf32(p1), u2 = f2tf32(p2), u3 = f2tf32(p3);
            uint32_t te, to;
            te = __shfl_sync(0xffffffffu, u0, srcLo); to = __shfl_sync(0xffffffffu, u1, srcLo);
            pf[nt][0] = sel ? to : te;
            te = __shfl_sync(0xffffffffu, u2, srcLo); to = __shfl_sync(0xffffffffu, u3, srcLo);
            pf[nt][1] = sel ? to : te;
            te = __shfl_sync(0xffffffffu, u0, srcHi); to = __shfl_sync(0xffffffffu, u1, srcHi);
            pf[nt][2] = sel ? to : te;
            te = __shfl_sync(0xffffffffu, u2, srcHi); to = __shfl_sync(0xffffffffu, u3, srcHi);
            pf[nt][3] = sel ? to : te;
        }
        rs0 += __shfl_xor_sync(0xffffffffu, rs0, 1);
        rs0 += __shfl_xor_sync(0xffffffffu, rs0, 2);
        rs1 += __shfl_xor_sync(0xffffffffu, rs1, 1);
        rs1 += __shfl_xor_sync(0xffffffffu, rs1, 2);
        l0r = l0r * c0f + rs0;
        l1r = l1r * c1f + rs1;
#pragma unroll
        for (int nt = 0; nt < 8; nt++) {
            o[nt][0] *= c0f; o[nt][1] *= c0f;
            o[nt][2] *= c1f; o[nt][3] *= c1f;
        }

        // ---- O += P @ V
#pragma unroll
        for (int ks = 0; ks < 8; ks++) {
            const uint32_t* vb0 = (const uint32_t*)(Vp + (ks * 8 + gc) * VS);
            const uint32_t* vb1 = (const uint32_t*)(Vp + (ks * 8 + gc + 4) * VS);
#pragma unroll
            for (int nt = 0; nt < 8; nt++)
                mma_tf32(o[nt], pf[ks], vb0[nt * 8 + gr], vb1[nt * 8 + gr]);
        }
        __syncthreads();
    }

    // ---- epilogue: normalize, write to g_ao (b, n, nh*64+c)
    const int b = bh / NHEAD, hh = bh % NHEAD;
    const float inv0 = 1.f / l0r, inv1 = 1.f / l1r;
    float* d0 = g_ao + (size_t)(b * NSEQ + q0 + wrow + gr) * DIMM + hh * HDIM + 2 * gc;
    float* d1 = d0 + (size_t)8 * DIMM;
#pragma unroll
    for (int nt = 0; nt < 8; nt++) {
        *(float2*)(d0 + nt * 8) = make_float2(o[nt][0] * inv0, o[nt][1] * inv0);
        *(float2*)(d1 + nt * 8) = make_float2(o[nt][2] * inv1, o[nt][3] * inv1);
    }
}

// =================================================================
extern "C" void kernel_launch(void* const* d_in, const int* in_sizes, int n_in,
                              void* d_out, int out_size)
{
    const float* x     = (const float*)d_in[0];
    const float* rph   = (const float*)d_in[1];
    const float* rpw   = (const float*)d_in[2];
    const float* qkvw  = (const float*)d_in[3];
    const float* qkvb  = (const float*)d_in[4];
    const float* projw = (const float*)d_in[5];
    const float* projb = (const float*)d_in[6];
    float* out = (float*)d_out;

    cudaFuncSetAttribute(flash_tc,   cudaFuncAttributeMaxDynamicSharedMemorySize, FLASH_TC_SMEM);
    cudaFuncSetAttribute(rel_kernel, cudaFuncAttributeMaxDynamicSharedMemorySize, REL_SMEM);

    // 1) QKV projection + head split (tf32, double-buffered)
    gemm_tc<0><<<dim3(2304 / 128, MROWS / 128), dim3(256)>>>(x, qkvw, qkvb, nullptr, 2304, DIMM);
    // 2) rel-pos bias tables
    rel_kernel<<<dim3(GRID_H, BHN), dim3(256), REL_SMEM>>>(rph, rpw);
    // 3) fused flash attention (tf32, double-buffered, reg-P, 2 CTA/SM)
    flash_tc<<<dim3(NSEQ / 128, BHN), dim3(256), FLASH_TC_SMEM>>>();
    // 4) output projection (tf32, double-buffered)
    gemm_tc<1><<<dim3(DIMM / 128, MROWS / 128), dim3(256)>>>(nullptr, projw, projb, out, DIMM, DIMM);
}

// round 6
// speedup vs baseline: 1.0495x; 1.0495x over previous
#include <cuda_runtime.h>
#include <cuda_bf16.h>
#include <math.h>
#include <stdint.h>

// Problem constants
#define DIMM   768
#define NHEAD  12
#define HDIM   64
#define BATCH  2
#define GRID_H 48
#define NSEQ   2304          // 48*48
#define BHN    24            // BATCH*NHEAD
#define MROWS  4608          // BATCH*NSEQ
#define SCALE  0.125f        // 64^-0.5

// ---------------- device scratch (static: no cudaMalloc allowed) ----------------
__device__ float g_q[BHN * NSEQ * HDIM];       // [bh][n][c], unscaled
__device__ float g_k[BHN * NSEQ * HDIM];
__device__ float g_v[BHN * NSEQ * HDIM];
__device__ float g_relh[BHN * NSEQ * GRID_H];  // [bh][q][kh]
__device__ float g_relw[BHN * NSEQ * GRID_H];  // [bh][q][kw]
__device__ float g_ao[MROWS * DIMM];           // attention output (b,n,dim)

// ---------------- tf32 helpers ----------------
__device__ __forceinline__ uint32_t f2tf32(float f) {
    uint32_t r;
    asm("cvt.rna.tf32.f32 %0, %1;" : "=r"(r) : "f"(f));
    return r;
}
__device__ __forceinline__ float tf32f(float f) { return __uint_as_float(f2tf32(f)); }

// D(16x8,f32) += A(16x8,tf32,row) * B(8x8,tf32,col)
__device__ __forceinline__ void mma_tf32(float* d, const uint32_t* a,
                                         uint32_t b0, uint32_t b1) {
    asm volatile(
        "mma.sync.aligned.m16n8k8.row.col.f32.tf32.tf32.f32 "
        "{%0,%1,%2,%3}, {%4,%5,%6,%7}, {%8,%9}, {%0,%1,%2,%3};"
        : "+f"(d[0]), "+f"(d[1]), "+f"(d[2]), "+f"(d[3])
        : "r"(a[0]), "r"(a[1]), "r"(a[2]), "r"(a[3]), "r"(b0), "r"(b1));
}

__device__ __forceinline__ void cp_async16(void* smem_dst, const void* gmem_src) {
    uint32_t s = (uint32_t)__cvta_generic_to_shared(smem_dst);
    asm volatile("cp.async.cg.shared.global [%0], [%1], 16;\n" :: "r"(s), "l"(gmem_src));
}
__device__ __forceinline__ void cp_commit() {
    asm volatile("cp.async.commit_group;\n");
}
__device__ __forceinline__ void cp_wait_all() {
    asm volatile("cp.async.wait_group 0;\n");
}

// =================================================================
// tf32 tensor-core GEMM NT, cp.async double-buffered (1 sync / k-step).
// SMEM holds raw fp32; tf32 cvt happens at fragment-load time.
// C[M,N] = A[M,K] * B[N,K]^T (+bias). 128x128x16 tiles, 8 warps.
// MODE 0: QKV epilogue scattering to g_q/g_k/g_v. MODE 1: A=g_ao.
// =================================================================
#define GPAD 20

template<int MODE>
__global__ __launch_bounds__(256, 2) void gemm_tc(const float* __restrict__ Aext,
                                                  const float* __restrict__ B,
                                                  const float* __restrict__ bias,
                                                  float* __restrict__ Cout,
                                                  int Ncol, int K)
{
    __shared__ float As[2][128][GPAD];
    __shared__ float Bs[2][128][GPAD];
    const float* A = (MODE == 0) ? Aext : (const float*)g_ao;

    const int m0 = blockIdx.y * 128;
    const int n0 = blockIdx.x * 128;
    const int tid = threadIdx.x;
    const int lane = tid & 31;
    const int wid = tid >> 5;
    const int wm = (wid & 1) * 64;   // warp m-offset
    const int wn = (wid >> 1) * 32;  // warp n-offset
    const int gr = lane >> 2;        // 0..7
    const int gc = lane & 3;         // 0..3
    const int sr = tid >> 2;         // staging row 0..63
    const int sc = (tid & 3) << 2;   // staging col 0,4,8,12

    float acc[4][4][4];
#pragma unroll
    for (int mi = 0; mi < 4; mi++)
#pragma unroll
        for (int ni = 0; ni < 4; ni++)
#pragma unroll
            for (int j = 0; j < 4; j++) acc[mi][ni][j] = 0.f;

    auto issue = [&](int k0, int pb) {
        cp_async16(&As[pb][sr][sc],      A + (size_t)(m0 + sr) * K + k0 + sc);
        cp_async16(&As[pb][sr + 64][sc], A + (size_t)(m0 + sr + 64) * K + k0 + sc);
        cp_async16(&Bs[pb][sr][sc],      B + (size_t)(n0 + sr) * K + k0 + sc);
        cp_async16(&Bs[pb][sr + 64][sc], B + (size_t)(n0 + sr + 64) * K + k0 + sc);
        cp_commit();
    };

    issue(0, 0);

    const int nk = K / 16;
    for (int kt = 0; kt < nk; kt++) {
        const int p = kt & 1;
        cp_wait_all();
        __syncthreads();
        // issue next tile; overlaps with compute below. Safe: buf p^1 was
        // last read in iter kt-1's compute, which all warps finished
        // (the sync above).
        if (kt + 1 < nk) issue((kt + 1) * 16, p ^ 1);

#pragma unroll
        for (int kk = 0; kk < 16; kk += 8) {
            uint32_t af[4][4], bf[4][2];
#pragma unroll
            for (int mi = 0; mi < 4; mi++) {
                const float* ap = &As[p][wm + mi * 16 + gr][kk + gc];
                af[mi][0] = f2tf32(ap[0]);
                af[mi][1] = f2tf32(ap[8 * GPAD]);
                af[mi][2] = f2tf32(ap[4]);
                af[mi][3] = f2tf32(ap[8 * GPAD + 4]);
            }
#pragma unroll
            for (int ni = 0; ni < 4; ni++) {
                const float* bp = &Bs[p][wn + ni * 8 + gr][kk + gc];
                bf[ni][0] = f2tf32(bp[0]);
                bf[ni][1] = f2tf32(bp[4]);
            }
#pragma unroll
            for (int mi = 0; mi < 4; mi++)
#pragma unroll
                for (int ni = 0; ni < 4; ni++)
                    mma_tf32(acc[mi][ni], af[mi], bf[ni][0], bf[ni][1]);
        }
    }

    // ---- epilogue
#pragma unroll
    for (int ni = 0; ni < 4; ni++) {
        const int nb = n0 + wn + ni * 8 + 2 * gc;
        const float bbx = bias[nb], bby = bias[nb + 1];
        if (MODE == 0) {
            const int p = nb / DIMM;
            const int hh = (nb % DIMM) / HDIM;
            const int cb = nb % HDIM;
            float* dst = (p == 0) ? g_q : ((p == 1) ? g_k : g_v);
#pragma unroll
            for (int mi = 0; mi < 4; mi++) {
                int m = m0 + wm + mi * 16 + gr;
                int b = m / NSEQ, nn = m % NSEQ;
                float* d0 = dst + (size_t)((b * NHEAD + hh) * NSEQ + nn) * HDIM + cb;
                *(float2*)d0 = make_float2(acc[mi][ni][0] + bbx, acc[mi][ni][1] + bby);
                int m2 = m + 8;
                int b2 = m2 / NSEQ, nn2 = m2 % NSEQ;
                float* d1 = dst + (size_t)((b2 * NHEAD + hh) * NSEQ + nn2) * HDIM + cb;
                *(float2*)d1 = make_float2(acc[mi][ni][2] + bbx, acc[mi][ni][3] + bby);
            }
        } else {
#pragma unroll
            for (int mi = 0; mi < 4; mi++) {
                int m = m0 + wm + mi * 16 + gr;
                *(float2*)(Cout + (size_t)m * Ncol + nb) =
                    make_float2(acc[mi][ni][0] + bbx, acc[mi][ni][1] + bby);
                *(float2*)(Cout + (size_t)(m + 8) * Ncol + nb) =
                    make_float2(acc[mi][ni][2] + bbx, acc[mi][ni][3] + bby);
            }
        }
    }
}

// =================================================================
// rel bias tables (unchanged)
// =================================================================
#define REL_SMEM ((3072 + 3072 + 6080) * 4)

__global__ __launch_bounds__(256) void rel_kernel(const float* __restrict__ rph,
                                                  const float* __restrict__ rpw)
{
    extern __shared__ float sm[];
    float* qs = sm;            // [48][64]
    float* rh = sm + 3072;     // [48][64]
    float* rw = sm + 6144;     // [95][64]

    const int qh = blockIdx.x;
    const int bh = blockIdx.y;
    const int tid = threadIdx.x;

    const float4* qsrc = (const float4*)(g_q + (size_t)(bh * NSEQ + qh * GRID_H) * HDIM);
#pragma unroll
    for (int i = 0; i < 3; i++) ((float4*)qs)[tid + i * 256] = qsrc[tid + i * 256];

    for (int i = tid; i < 768; i += 256) {
        int kh = i >> 4, cc = i & 15;
        ((float4*)rh)[i] = ((const float4*)(rph + (size_t)(qh - kh + 47) * HDIM))[cc];
    }
    for (int i = tid; i < 1520; i += 256) ((float4*)rw)[i] = ((const float4*)rpw)[i];
    __syncthreads();

    for (int idx = tid; idx < 2304; idx += 256) {
        int qw = idx / GRID_H;
        int kk = idx - qw * GRID_H;
        const float4* qp = (const float4*)(qs + qw * HDIM);
        const float4* hp = (const float4*)(rh + kk * HDIM);
        const float4* wp = (const float4*)(rw + (qw - kk + 47) * HDIM);
        float sh = 0.f, sw2 = 0.f;
#pragma unroll
        for (int c = 0; c < 16; c++) {
            float4 a = qp[c], hb = hp[c], wb = wp[c];
            sh  += a.x * hb.x + a.y * hb.y + a.z * hb.z + a.w * hb.w;
            sw2 += a.x * wb.x + a.y * wb.y + a.z * wb.z + a.w * wb.w;
        }
        size_t base = ((size_t)bh * NSEQ + (size_t)qh * GRID_H + qw) * GRID_H + kk;
        g_relh[base] = sh;
        g_relw[base] = sw2;
    }
}

// =================================================================
// Flash attention, tf32 mma, double-buffered K/V with register
// prefetch (1 sync/iter, LDG hidden behind full compute phase),
// P in registers via fragment shuffle, bf16 rel bias.
// 128-q tile, 8 warps. No reg cap (avoid spills).
// =================================================================
#define KS 68   // ≡ 4 (mod 32)
#define VS 72   // ≡ 8 (mod 32)
#define RLS 52
#define FLASH_TC_SMEM (2*64*KS*4 + 2*64*VS*4 + 2*128*RLS*2)

__global__ __launch_bounds__(256) void flash_tc()
{
    extern __shared__ char smraw[];
    float* Kb = (float*)smraw;                          // [2][64*KS]
    float* Vb = (float*)(smraw + 2 * 64 * KS * 4);      // [2][64*VS]
    __nv_bfloat16* RHb = (__nv_bfloat16*)(smraw + 2 * 64 * KS * 4 + 2 * 64 * VS * 4);
    __nv_bfloat16* RWb = RHb + 128 * RLS;

    const int bh = blockIdx.y;
    const int q0 = blockIdx.x * 128;
    const int tid = threadIdx.x;
    const int lane = tid & 31;
    const int wid = tid >> 5;
    const int wrow = wid * 16;          // warp's q-row stripe base (tile-local)
    const int gr = lane >> 2;           // 0..7
    const int gc = lane & 3;            // 0..3
    const int srcLo = 4 * gr + (gc >> 1);
    const int srcHi = srcLo + 2;
    const int sel = gc & 1;

    const float* qg = g_q + (size_t)bh * NSEQ * HDIM;
    const float* kg = g_k + (size_t)bh * NSEQ * HDIM;
    const float* vg = g_v + (size_t)bh * NSEQ * HDIM;

    const int ldrow = tid >> 2;          // 0..63 (K/V staging row)
    const int ldc0 = (tid & 3) * 16;     // 16-col slice

    float4 kpre[4], vpre[4];
    auto ldg = [&](int tile) {
        const float* krow = kg + ((size_t)(tile * 64 + ldrow)) * HDIM + ldc0;
        const float* vrow = vg + ((size_t)(tile * 64 + ldrow)) * HDIM + ldc0;
#pragma unroll
        for (int i = 0; i < 4; i++) {
            kpre[i] = *(const float4*)(krow + i * 4);
            vpre[i] = *(const float4*)(vrow + i * 4);
        }
    };
    auto sts = [&](int pb) {
        float* kd = Kb + pb * 64 * KS + ldrow * KS + ldc0;
        float* vd = Vb + pb * 64 * VS + ldrow * VS + ldc0;
#pragma unroll
        for (int i = 0; i < 4; i++) {
            *(float4*)(kd + i * 4) = make_float4(tf32f(kpre[i].x), tf32f(kpre[i].y),
                                                 tf32f(kpre[i].z), tf32f(kpre[i].w));
            *(float4*)(vd + i * 4) = make_float4(tf32f(vpre[i].x), tf32f(vpre[i].y),
                                                 tf32f(vpre[i].z), tf32f(vpre[i].w));
        }
    };

    // ---- Q fragments: scaled, tf32-rounded, registers for all iters
    uint32_t qa[8][4];
    {
        const float* qr0 = qg + (size_t)(q0 + wrow + gr) * HDIM;
        const float* qr1 = qr0 + 8 * HDIM;
#pragma unroll
        for (int ks = 0; ks < 8; ks++) {
            qa[ks][0] = f2tf32(qr0[ks * 8 + gc] * SCALE);
            qa[ks][1] = f2tf32(qr1[ks * 8 + gc] * SCALE);
            qa[ks][2] = f2tf32(qr0[ks * 8 + gc + 4] * SCALE);
            qa[ks][3] = f2tf32(qr1[ks * 8 + gc + 4] * SCALE);
        }
    }

    // ---- rel bias slices -> bf16 SMEM [128][48] (stride 52)
    {
        const float4* srcH = (const float4*)(g_relh + ((size_t)bh * NSEQ + q0) * GRID_H);
        const float4* srcW = (const float4*)(g_relw + ((size_t)bh * NSEQ + q0) * GRID_H);
        for (int i = tid; i < 1536; i += 256) {   // 128 rows * 12 float4/row
            int r = i / 12, c4 = i % 12;
            float4 vh = srcH[i], vw = srcW[i];
            __nv_bfloat162* dh = (__nv_bfloat162*)(RHb + r * RLS + c4 * 4);
            __nv_bfloat162* dw = (__nv_bfloat162*)(RWb + r * RLS + c4 * 4);
            dh[0] = __floats2bfloat162_rn(vh.x, vh.y);
            dh[1] = __floats2bfloat162_rn(vh.z, vh.w);
            dw[0] = __floats2bfloat162_rn(vw.x, vw.y);
            dw[1] = __floats2bfloat162_rn(vw.z, vw.w);
        }
    }

    ldg(0);   // prefetch tile 0 into registers

    float o[8][4];
    float m0r = -1e30f, m1r = -1e30f, l0r = 0.f, l1r = 0.f;
#pragma unroll
    for (int nt = 0; nt < 8; nt++)
#pragma unroll
        for (int j = 0; j < 4; j++) o[nt][j] = 0.f;

    const int NIT = NSEQ / 64;   // 36
    for (int it = 0; it < NIT; it++) {
        const int p = it & 1;
        sts(p);                           // store prefetched tile
        if (it + 1 < NIT) ldg(it + 1);    // LDG next: hidden behind compute
        __syncthreads();
        // Safe: buf p last read at iter it-2's compute, before sync@it-1.

        const float* Kp = Kb + p * 64 * KS;
        const float* Vp = Vb + p * 64 * VS;
        const int k0 = it * 64;

        // ---- S = Q @ K^T
        float s[8][4];
#pragma unroll
        for (int nt = 0; nt < 8; nt++) {
            s[nt][0] = s[nt][1] = s[nt][2] = s[nt][3] = 0.f;
            const uint32_t* kb = (const uint32_t*)(Kp + (nt * 8 + gr) * KS);
#pragma unroll
            for (int ks = 0; ks < 8; ks++)
                mma_tf32(s[nt], qa[ks], kb[ks * 8 + gc], kb[ks * 8 + gc + 4]);
        }

        // ---- add decomposed rel-pos bias (bf16)
        {
            const __nv_bfloat16* rh0 = RHb + (wrow + gr) * RLS;
            const __nv_bfloat16* rw0 = RWb + (wrow + gr) * RLS;
            const __nv_bfloat16* rh1 = rh0 + 8 * RLS;
            const __nv_bfloat16* rw1 = rw0 + 8 * RLS;
#pragma unroll
            for (int nt = 0; nt < 8; nt++) {
                int c0 = k0 + nt * 8 + 2 * gc;
                int kh0 = c0 / GRID_H, kw0 = c0 - kh0 * GRID_H;
                int c1 = c0 + 1;
                int kh1 = c1 / GRID_H, kw1 = c1 - kh1 * GRID_H;
                s[nt][0] += __bfloat162float(rh0[kh0]) + __bfloat162float(rw0[kw0]);
                s[nt][1] += __bfloat162float(rh0[kh1]) + __bfloat162float(rw0[kw1]);
                s[nt][2] += __bfloat162float(rh1[kh0]) + __bfloat162float(rw1[kw0]);
                s[nt][3] += __bfloat162float(rh1[kh1]) + __bfloat162float(rw1[kw1]);
            }
        }

        // ---- online softmax (rows wrow+gr, wrow+gr+8)
        float t0 = -1e30f, t1 = -1e30f;
#pragma unroll
        for (int nt = 0; nt < 8; nt++) {
            t0 = fmaxf(t0, fmaxf(s[nt][0], s[nt][1]));
            t1 = fmaxf(t1, fmaxf(s[nt][2], s[nt][3]));
        }
        t0 = fmaxf(t0, __shfl_xor_sync(0xffffffffu, t0, 1));
        t0 = fmaxf(t0, __shfl_xor_sync(0xffffffffu, t0, 2));
        t1 = fmaxf(t1, __shfl_xor_sync(0xffffffffu, t1, 1));
        t1 = fmaxf(t1, __shfl_xor_sync(0xffffffffu, t1, 2));

        float mn0 = fmaxf(m0r, t0), mn1 = fmaxf(m1r, t1);
        float c0f = __expf(m0r - mn0), c1f = __expf(m1r - mn1);
        m0r = mn0; m1r = mn1;

        // ---- exp, row-sum, and P -> A-fragment layout via shuffles
        uint32_t pf[8][4];
        float rs0 = 0.f, rs1 = 0.f;
#pragma unroll
        for (int nt = 0; nt < 8; nt++) {
            float p0 = __expf(s[nt][0] - mn0);
            float p1 = __expf(s[nt][1] - mn0);
            float p2 = __expf(s[nt][2] - mn1);
            float p3 = __expf(s[nt][3] - mn1);
            rs0 += p0 + p1;
            rs1 += p2 + p3;
            uint32_t u0 = f2tf32(p0), u1 = f2tf32(p1), u2 = f2tf32(p2), u3 = f2tf32(p3);
            uint32_t te, to;
            te = __shfl_sync(0xffffffffu, u0, srcLo); to = __shfl_sync(0xffffffffu, u1, srcLo);
            pf[nt][0] = sel ? to : te;
            te = __shfl_sync(0xffffffffu, u2, srcLo); to = __shfl_sync(0xffffffffu, u3, srcLo);
            pf[nt][1] = sel ? to : te;
            te = __shfl_sync(0xffffffffu, u0, srcHi); to = __shfl_sync(0xffffffffu, u1, srcHi);
            pf[nt][2] = sel ? to : te;
            te = __shfl_sync(0xffffffffu, u2, srcHi); to = __shfl_sync(0xffffffffu, u3, srcHi);
            pf[nt][3] = sel ? to : te;
        }
        rs0 += __shfl_xor_sync(0xffffffffu, rs0, 1);
        rs0 += __shfl_xor_sync(0xffffffffu, rs0, 2);
        rs1 += __shfl_xor_sync(0xffffffffu, rs1, 1);
        rs1 += __shfl_xor_sync(0xffffffffu, rs1, 2);
        l0r = l0r * c0f + rs0;
        l1r = l1r * c1f + rs1;
#pragma unroll
        for (int nt = 0; nt < 8; nt++) {
            o[nt][0] *= c0f; o[nt][1] *= c0f;
            o[nt][2] *= c1f; o[nt][3] *= c1f;
        }

        // ---- O += P @ V
#pragma unroll
        for (int ks = 0; ks < 8; ks++) {
            const uint32_t* vb0 = (const uint32_t*)(Vp + (ks * 8 + gc) * VS);
            const uint32_t* vb1 = (const uint32_t*)(Vp + (ks * 8 + gc + 4) * VS);
#pragma unroll
            for (int nt = 0; nt < 8; nt++)
                mma_tf32(o[nt], pf[ks], vb0[nt * 8 + gr], vb1[nt * 8 + gr]);
        }
    }

    // ---- epilogue: normalize, write to g_ao (b, n, nh*64+c)
    const int b = bh / NHEAD, hh = bh % NHEAD;
    const float inv0 = 1.f / l0r, inv1 = 1.f / l1r;
    float* d0 = g_ao + (size_t)(b * NSEQ + q0 + wrow + gr) * DIMM + hh * HDIM + 2 * gc;
    float* d1 = d0 + (size_t)8 * DIMM;
#pragma unroll
    for (int nt = 0; nt < 8; nt++) {
        *(float2*)(d0 + nt * 8) = make_float2(o[nt][0] * inv0, o[nt][1] * inv0);
        *(float2*)(d1 + nt * 8) = make_float2(o[nt][2] * inv1, o[nt][3] * inv1);
    }
}

// =================================================================
extern "C" void kernel_launch(void* const* d_in, const int* in_sizes, int n_in,
                              void* d_out, int out_size)
{
    const float* x     = (const float*)d_in[0];
    const float* rph   = (const float*)d_in[1];
    const float* rpw   = (const float*)d_in[2];
    const float* qkvw  = (const float*)d_in[3];
    const float* qkvb  = (const float*)d_in[4];
    const float* projw = (const float*)d_in[5];
    const float* projb = (const float*)d_in[6];
    float* out = (float*)d_out;

    cudaFuncSetAttribute(flash_tc,   cudaFuncAttributeMaxDynamicSharedMemorySize, FLASH_TC_SMEM);
    cudaFuncSetAttribute(rel_kernel, cudaFuncAttributeMaxDynamicSharedMemorySize, REL_SMEM);

    // 1) QKV projection + head split (tf32, cp.async double-buffered)
    gemm_tc<0><<<dim3(2304 / 128, MROWS / 128), dim3(256)>>>(x, qkvw, qkvb, nullptr, 2304, DIMM);
    // 2) rel-pos bias tables
    rel_kernel<<<dim3(GRID_H, BHN), dim3(256), REL_SMEM>>>(rph, rpw);
    // 3) fused flash attention (tf32, double-buffered, reg-prefetch)
    flash_tc<<<dim3(NSEQ / 128, BHN), dim3(256), FLASH_TC_SMEM>>>();
    // 4) output projection (tf32, cp.async double-buffered)
    gemm_tc<1><<<dim3(DIMM / 128, MROWS / 128), dim3(256)>>>(nullptr, projw, projb, out, DIMM, DIMM);
}